// round 4
// baseline (speedup 1.0000x reference)
#include <cuda_runtime.h>
#include <cuda_bf16.h>
#include <stdint.h>

#define BATCH 16384
#define KS 20
#define DIM 256
#define NH 4
#define EPSF 1e-8f

typedef __nv_bfloat16 bf16;

// ---------------- scratch (device globals; allocations are forbidden) ------
// bf16 hi/lo activation pairs
__device__ bf16 g_xh [(long)BATCH * 256], g_xl [(long)BATCH * 256];
__device__ bf16 g_c2h[(long)BATCH * 512], g_c2l[(long)BATCH * 512];
__device__ bf16 g_qh [(long)BATCH * 256], g_ql [(long)BATCH * 256];
__device__ bf16 g_sh [(long)BATCH * 1024], g_sl [(long)BATCH * 1024];
__device__ bf16 g_ch [(long)BATCH * 256], g_cl [(long)BATCH * 256];
// converted weights (hi/lo), layout described in conv_w
#define W_TOTAL 425984
__device__ bf16 g_wh[W_TOTAL], g_wl[W_TOTAL];
// fp32 intermediates
__device__ float g_had [(long)BATCH * 128];
__device__ float g_himp[(long)BATCH * 256];
__device__ float g_qk  [(long)BATCH * 1024];
__device__ float g_stat[BATCH];
__device__ float g_anom[BATCH];

__device__ __forceinline__ float warp_sum(float v) {
    #pragma unroll
    for (int o = 16; o; o >>= 1) v += __shfl_down_sync(0xffffffffu, v, o);
    return v;
}

__device__ __forceinline__ void store_split(bf16* ph, bf16* pl, float v) {
    bf16 h = __float2bfloat16(v);
    *ph = h;
    *pl = __float2bfloat16(v - __bfloat162float(h));
}

// ---------------- conv_w: one-shot weight conversion (+ Wk transpose) ------
// layout in g_wh/g_wl:
//   [0,32768)        ad_w1   [128][256]
//   [32768,163840)   imp_w1  [256][512]
//   [163840,229376)  wq      [256][256]
//   [229376,294912)  wkT     [4][256 n][64 i]   (transposed)
//   [294912,360448)  wv      [256][256]
//   [360448,425984)  w_out   [256][256]
__global__ __launch_bounds__(256) void conv_w(
    const float* __restrict__ ad_w1, const float* __restrict__ imp_w1,
    const float* __restrict__ w_in,  const float* __restrict__ w_out)
{
    int i = blockIdx.x * 256 + threadIdx.x;
    if (i >= W_TOTAL) return;
    float v;
    if (i < 32768)       v = ad_w1[i];
    else if (i < 163840) v = imp_w1[i - 32768];
    else if (i < 229376) v = w_in[i - 163840];
    else if (i < 294912) {
        int j = i - 229376;
        int z = j >> 14, r = (j >> 6) & 255, c = j & 63;
        v = w_in[65536 + (z * 64 + c) * 256 + r];
    }
    else if (i < 360448) v = w_in[131072 + (i - 294912)];
    else                 v = w_out[i - 360448];
    bf16 h = __float2bfloat16(v);
    g_wh[i] = h;
    g_wl[i] = __float2bfloat16(v - __bfloat162float(h));
}

// ---------------- K1: stats + stat anomaly + st rows 1..19 + bf16 exports --
__global__ __launch_bounds__(256) void k1_stats(
    const float* __restrict__ storage, const float* __restrict__ xmsg,
    float* __restrict__ out_st)
{
    __shared__ float sm[KS][DIM];
    __shared__ float smask[KS];
    __shared__ float sred[8];

    int b = blockIdx.x, tid = threadIdx.x;
    const float* row = storage + (long)b * KS * DIM;
    #pragma unroll
    for (int j = 0; j < KS; j++) sm[j][tid] = row[j * DIM + tid];
    __syncthreads();

    int w = tid >> 5, lane = tid & 31;
    for (int j = w; j < KS; j += 8) {
        float s = 0.f;
        #pragma unroll
        for (int i = lane; i < DIM; i += 32) s += fabsf(sm[j][i]);
        s = warp_sum(s);
        if (lane == 0) smask[j] = (s > 0.f) ? 1.f : 0.f;
    }
    __syncthreads();

    float denom = EPSF;
    #pragma unroll
    for (int j = 0; j < KS; j++) denom += smask[j];

    int d = tid;
    float m = 0.f;
    #pragma unroll
    for (int j = 0; j < KS; j++) m += sm[j][d] * smask[j];
    float hmean = m / denom;
    float v = 0.f;
    #pragma unroll
    for (int j = 0; j < KS; j++) {
        float df = sm[j][d] - hmean;
        v += df * df * smask[j];
    }
    float hstd = sqrtf(v / denom);

    float xd = xmsg[(long)b * DIM + d];
    float z = fabsf((xd - hmean) / (hstd + EPSF));
    float c = (z > 2.0f) ? 1.f : 0.f;
    c = warp_sum(c);
    if (lane == 0) sred[w] = c;
    __syncthreads();
    if (tid == 0) {
        float t = 0.f;
        #pragma unroll
        for (int i = 0; i < 8; i++) t += sred[i];
        g_stat[b] = t / (float)DIM;
    }

    store_split(g_xh + (long)b * 256 + d, g_xl + (long)b * 256 + d, xd);
    store_split(g_c2h + (long)b * 512 + d, g_c2l + (long)b * 512 + d, xd);
    store_split(g_c2h + (long)b * 512 + 256 + d,
                g_c2l + (long)b * 512 + 256 + d, hmean);

    float dec = 1.f;
    float* orow = out_st + (long)b * KS * DIM;
    #pragma unroll
    for (int j = 1; j < KS; j++) {
        orow[j * DIM + d] = sm[j - 1][d] * dec;
        dec *= 0.95f;
    }
}

// ---------------- K2: learned anomaly + combine ----------------------------
__global__ __launch_bounds__(256) void k2_anom(
    const float* __restrict__ ad_w2, const float* __restrict__ ad_b2)
{
    int w = threadIdx.x >> 5, lane = threadIdx.x & 31;
    int row = blockIdx.x * 8 + w;
    const float* h = g_had + (long)row * 128;
    float s = 0.f;
    #pragma unroll
    for (int i = lane; i < 128; i += 32) s += h[i] * ad_w2[i];
    s = warp_sum(s);
    if (lane == 0) {
        float t = s + ad_b2[0];
        float learned = 1.f / (1.f + expf(-t));
        g_anom[row] = 0.5f * g_stat[row] + 0.5f * learned;
    }
}

// ---------------- K4: importance + st row 0 --------------------------------
__global__ __launch_bounds__(256) void k4_imp(
    const float* __restrict__ imp_w2, const float* __restrict__ imp_b2,
    const float* __restrict__ xmsg, float* __restrict__ out_st)
{
    __shared__ float sred[8];
    __shared__ float simp;
    int b = blockIdx.x, d = threadIdx.x;
    int w = d >> 5, lane = d & 31;
    float p = g_himp[(long)b * DIM + d] * imp_w2[d];
    p = warp_sum(p);
    if (lane == 0) sred[w] = p;
    __syncthreads();
    if (d == 0) {
        float t = imp_b2[0];
        #pragma unroll
        for (int i = 0; i < 8; i++) t += sred[i];
        float sp = fmaxf(t, 0.f) + log1pf(expf(-fabsf(t)));
        simp = sp * (1.f + g_anom[b]);
    }
    __syncthreads();
    out_st[(long)b * KS * DIM + d] = xmsg[(long)b * DIM + d] * simp;
}

// ---------------- K7: scores -> softmax -> weighted sums (bf16 out) --------
__global__ __launch_bounds__(256) void k7_attn(const float* __restrict__ out_st)
{
    __shared__ float st_s[KS][DIM];
    __shared__ float qk_s[NH][DIM];
    __shared__ float sc[NH][KS];

    int b = blockIdx.x, tid = threadIdx.x;
    const float* srow = out_st + (long)b * KS * DIM;
    #pragma unroll
    for (int j = 0; j < KS; j++) st_s[j][tid] = srow[j * DIM + tid];
    #pragma unroll
    for (int h = 0; h < NH; h++)
        qk_s[h][tid] = g_qk[(long)b * 1024 + h * DIM + tid];
    __syncthreads();

    int w = tid >> 5, lane = tid & 31;
    for (int id = w; id < NH * KS; id += 8) {
        int h = id / KS, j = id % KS;
        float s = 0.f;
        #pragma unroll
        for (int i = lane; i < DIM; i += 32) s += qk_s[h][i] * st_s[j][i];
        s = warp_sum(s);
        if (lane == 0) sc[h][j] = s * 0.125f;   // 1/sqrt(64)
    }
    __syncthreads();

    if (tid < NH) {
        float mx = -1e30f;
        #pragma unroll
        for (int j = 0; j < KS; j++) mx = fmaxf(mx, sc[tid][j]);
        float su = 0.f;
        #pragma unroll
        for (int j = 0; j < KS; j++) {
            float e = expf(sc[tid][j] - mx);
            sc[tid][j] = e; su += e;
        }
        float inv = 1.f / su;
        #pragma unroll
        for (int j = 0; j < KS; j++) sc[tid][j] *= inv;
    }
    __syncthreads();

    int d = tid;
    #pragma unroll
    for (int h = 0; h < NH; h++) {
        float a = 0.f;
        #pragma unroll
        for (int j = 0; j < KS; j++) a += sc[h][j] * st_s[j][d];
        long o = (long)b * 1024 + h * 256 + d;
        store_split(g_sh + o, g_sl + o, a);
    }
}

// ---------------- bf16x3 TC GEMM, 128x64 tile, ldmatrix --------------------
// C[m, cZ*z + n0+n] = act( sum_k A[m*lda + aZ*z + k] * B(k,n) + bias )
// A: bf16 hi/lo pair selected by aSel; B: g_wh/g_wl at wOff, [n][k] rows
#define KPAD 40

__device__ __forceinline__ void ldmx4(uint32_t* r, uint32_t addr) {
    asm volatile("ldmatrix.sync.aligned.m8n8.x4.shared.b16 {%0,%1,%2,%3},[%4];"
                 : "=r"(r[0]), "=r"(r[1]), "=r"(r[2]), "=r"(r[3]) : "r"(addr));
}
__device__ __forceinline__ void mma16816(float* c, const uint32_t* a,
                                         const uint32_t* b) {
    asm volatile(
        "mma.sync.aligned.m16n8k16.row.col.f32.bf16.bf16.f32 "
        "{%0,%1,%2,%3},{%4,%5,%6,%7},{%8,%9},{%0,%1,%2,%3};"
        : "+f"(c[0]), "+f"(c[1]), "+f"(c[2]), "+f"(c[3])
        : "r"(a[0]), "r"(a[1]), "r"(a[2]), "r"(a[3]), "r"(b[0]), "r"(b[1]));
}

__global__ __launch_bounds__(256) void gemm_tc(
    int aSel, int lda, int aZ,
    int wOff, int ldb, int bZ,
    const float* __restrict__ bias, int biasZ,
    float* __restrict__ Cext, int cSel, int cBfSel,
    int ldc, int cZ, int Ktot, int act)
{
    __shared__ bf16 Ahs[128][KPAD], Als[128][KPAD];
    __shared__ bf16 Bhs[64][KPAD],  Bls[64][KPAD];

    const bf16 *Ah, *Al;
    switch (aSel) {
        case 1:  Ah = g_xh;  Al = g_xl;  break;
        case 2:  Ah = g_c2h; Al = g_c2l; break;
        case 3:  Ah = g_qh;  Al = g_ql;  break;
        case 4:  Ah = g_sh;  Al = g_sl;  break;
        default: Ah = g_ch;  Al = g_cl;  break;
    }
    float* Cf = Cext;
    if (cSel == 2) Cf = g_had;
    else if (cSel == 3) Cf = g_himp;
    else if (cSel == 5) Cf = g_qk;

    int z  = blockIdx.z;
    int m0 = blockIdx.x * 128;
    int n0 = blockIdx.y * 64;
    long aOff = (long)aZ * z;
    long bOff = (long)wOff + (long)bZ * z;

    int tid = threadIdx.x;
    int warp = tid >> 5, lane = tid & 31;
    int wm = (warp >> 1) * 32, wn = (warp & 1) * 32;
    int lr = lane >> 2, lc = lane & 3;

    float acc[2][4][4];
    #pragma unroll
    for (int i = 0; i < 2; i++)
        #pragma unroll
        for (int j = 0; j < 4; j++)
            #pragma unroll
            for (int q = 0; q < 4; q++) acc[i][j][q] = 0.f;

    for (int c0 = 0; c0 < Ktot; c0 += 32) {
        // A tiles: 128x32 hi + lo
        {
            int row = tid >> 1, seg = (tid & 1) * 16;
            long gp = (long)(m0 + row) * lda + aOff + c0 + seg;
            *(uint4*)&Ahs[row][seg]     = *(const uint4*)(Ah + gp);
            *(uint4*)&Ahs[row][seg + 8] = *(const uint4*)(Ah + gp + 8);
            *(uint4*)&Als[row][seg]     = *(const uint4*)(Al + gp);
            *(uint4*)&Als[row][seg + 8] = *(const uint4*)(Al + gp + 8);
        }
        // B tiles: 64x32 hi (threads 0-127), lo (threads 128-255)
        {
            int t = tid & 127;
            int row = t >> 1, seg = (t & 1) * 16;
            long gp = bOff + (long)(n0 + row) * ldb + c0 + seg;
            if (tid < 128) {
                *(uint4*)&Bhs[row][seg]     = *(const uint4*)(g_wh + gp);
                *(uint4*)&Bhs[row][seg + 8] = *(const uint4*)(g_wh + gp + 8);
            } else {
                *(uint4*)&Bls[row][seg]     = *(const uint4*)(g_wl + gp);
                *(uint4*)&Bls[row][seg + 8] = *(const uint4*)(g_wl + gp + 8);
            }
        }
        __syncthreads();

        #pragma unroll
        for (int ks = 0; ks < 2; ks++) {
            int k0 = ks * 16;
            uint32_t ah[2][4], al[2][4], bh[2][4], bl[2][4];
            int arow = (lane & 15), akk = k0 + (lane >> 4) * 8;
            #pragma unroll
            for (int am = 0; am < 2; am++) {
                uint32_t ad = (uint32_t)__cvta_generic_to_shared(
                    &Ahs[wm + am * 16 + arow][akk]);
                ldmx4(ah[am], ad);
                uint32_t ad2 = (uint32_t)__cvta_generic_to_shared(
                    &Als[wm + am * 16 + arow][akk]);
                ldmx4(al[am], ad2);
            }
            int brow = ((lane >> 4) << 3) + (lane & 7);
            int bkk = k0 + ((lane >> 3) & 1) * 8;
            #pragma unroll
            for (int anp = 0; anp < 2; anp++) {
                uint32_t bd = (uint32_t)__cvta_generic_to_shared(
                    &Bhs[wn + anp * 16 + brow][bkk]);
                ldmx4(bh[anp], bd);
                uint32_t bd2 = (uint32_t)__cvta_generic_to_shared(
                    &Bls[wn + anp * 16 + brow][bkk]);
                ldmx4(bl[anp], bd2);
            }
            #pragma unroll
            for (int am = 0; am < 2; am++)
                #pragma unroll
                for (int an = 0; an < 4; an++) {
                    const uint32_t* bph = &bh[an >> 1][(an & 1) * 2];
                    const uint32_t* bpl = &bl[an >> 1][(an & 1) * 2];
                    mma16816(acc[am][an], ah[am], bph);
                    mma16816(acc[am][an], ah[am], bpl);
                    mma16816(acc[am][an], al[am], bph);
                }
        }
        __syncthreads();
    }

    // ---- epilogue ----
    #pragma unroll
    for (int am = 0; am < 2; am++) {
        #pragma unroll
        for (int an = 0; an < 4; an++) {
            int row0 = m0 + wm + am * 16 + lr;
            int col  = n0 + wn + an * 8 + lc * 2;
            float b0 = 0.f, b1 = 0.f;
            if (bias) {
                b0 = bias[biasZ * z + col];
                b1 = bias[biasZ * z + col + 1];
            }
            float v0 = acc[am][an][0] + b0, v1 = acc[am][an][1] + b1;
            float v2 = acc[am][an][2] + b0, v3 = acc[am][an][3] + b1;
            if (act == 1) {
                v0 = fmaxf(v0, 0.f); v1 = fmaxf(v1, 0.f);
                v2 = fmaxf(v2, 0.f); v3 = fmaxf(v3, 0.f);
            }
            long off = (long)cZ * z + col;
            if (cBfSel) {
                bf16* Ch = (cBfSel == 1) ? g_qh : g_ch;
                bf16* Cl = (cBfSel == 1) ? g_ql : g_cl;
                long p0 = (long)row0 * ldc + off;
                long p1 = (long)(row0 + 8) * ldc + off;
                store_split(Ch + p0, Cl + p0, v0);
                store_split(Ch + p0 + 1, Cl + p0 + 1, v1);
                store_split(Ch + p1, Cl + p1, v2);
                store_split(Ch + p1 + 1, Cl + p1 + 1, v3);
            } else {
                *(float2*)(Cf + (long)row0 * ldc + off) = make_float2(v0, v1);
                *(float2*)(Cf + (long)(row0 + 8) * ldc + off) = make_float2(v2, v3);
            }
        }
    }
}

// ---------------------------------------------------------------------------
extern "C" void kernel_launch(void* const* d_in, const int* in_sizes, int n_in,
                              void* d_out, int out_size) {
    const float* storage = (const float*)d_in[0];
    const float* x       = (const float*)d_in[1];
    const float* ad_w1   = (const float*)d_in[2];
    const float* ad_b1   = (const float*)d_in[3];
    const float* ad_w2   = (const float*)d_in[4];
    const float* ad_b2   = (const float*)d_in[5];
    const float* imp_w1  = (const float*)d_in[6];
    const float* imp_b1  = (const float*)d_in[7];
    const float* imp_w2  = (const float*)d_in[8];
    const float* imp_b2  = (const float*)d_in[9];
    const float* w_in    = (const float*)d_in[10];
    const float* b_in    = (const float*)d_in[11];
    const float* w_out   = (const float*)d_in[12];
    const float* b_out   = (const float*)d_in[13];

    float* st  = (float*)d_out;                       // [B,K,D]
    float* agg = st + (long)BATCH * KS * DIM;         // [B,D]

    conv_w<<<(W_TOTAL + 255) / 256, 256>>>(ad_w1, imp_w1, w_in, w_out);
    k1_stats<<<BATCH, 256>>>(storage, x, st);
    // ad-MLP hidden: relu(x @ ad_w1^T + ad_b1) -> g_had [B,128]
    gemm_tc<<<dim3(128, 2, 1), 256>>>(1, 256, 0, 0, 256, 0,
                                      ad_b1, 0, nullptr, 2, 0, 128, 0, 256, 1);
    k2_anom<<<BATCH / 8, 256>>>(ad_w2, ad_b2);
    // imp-MLP hidden: relu(ctx2 @ imp_w1^T + imp_b1) -> g_himp [B,256]
    gemm_tc<<<dim3(128, 4, 1), 256>>>(2, 512, 0, 32768, 512, 0,
                                      imp_b1, 0, nullptr, 3, 0, 256, 0, 512, 1);
    k4_imp<<<BATCH, 256>>>(imp_w2, imp_b2, x, st);
    // q = x @ wq^T + bq -> g_qh/g_ql [B,256]
    gemm_tc<<<dim3(128, 4, 1), 256>>>(1, 256, 0, 163840, 256, 0,
                                      b_in, 0, nullptr, 0, 1, 256, 0, 256, 0);
    // qk[b, z*256+n] = sum_i wkT[z][n][i] * q[b, z*64+i] -> g_qk fp32
    gemm_tc<<<dim3(128, 4, 4), 256>>>(3, 256, 64, 229376, 64, 16384,
                                      nullptr, 0, nullptr, 5, 0, 1024, 256, 64, 0);
    k7_attn<<<BATCH, 256>>>(st);
    // ctx[b, z*64+n] = wv_z[n,:] . s[b,z,:] + bv -> g_ch/g_cl [B,256]
    gemm_tc<<<dim3(128, 1, 4), 256>>>(4, 1024, 256, 294912, 256, 16384,
                                      b_in + 512, 64, nullptr, 0, 2, 256, 64, 256, 0);
    // agg = ctx @ attn_out_w^T + attn_out_b -> d_out tail (fp32)
    gemm_tc<<<dim3(128, 4, 1), 256>>>(5, 256, 0, 360448, 256, 0,
                                      b_out, 0, agg, 0, 0, 256, 0, 256, 0);
    (void)in_sizes; (void)n_in; (void)out_size;
}